// round 1
// baseline (speedup 1.0000x reference)
#include <cuda_runtime.h>
#include <math.h>

#define SLOPE 0.01f

// Problem constants (fixed by the dataset)
constexpr int Dd   = 32;
constexpr int Hh   = 128;
constexpr int INk  = 65;
constexpr int Bb   = 64;
constexpr int Tt   = 514;
constexpr int TTt  = 512;                 // T - LAGS
constexpr int NTOT = Bb * TTt;            // 32768
constexpr int NTILE = 64;
constexpr int NTILES = NTOT / NTILE;      // 512

constexpr int W1S = 68;                   // padded W1 row stride (floats), mult of 4
constexpr int GSS = 132;                  // padded g row stride (floats), mult of 4

// Output layout: outputs concatenated in reference return order
constexpr size_t RES_OFF  = 0;                               // (64,512,32)
constexpr size_t SUM_OFF  = (size_t)Bb * TTt * Dd;           // 1048576, (64,)
constexpr size_t HIST_OFF = SUM_OFF + Bb;                    // 1048640, (32,32768,1,64)

// Shared layout (floats):
//   W1s : 128*68  = 8704
//   xs  : 66*32   = 2112
//   gs  : 64*132  = 8448
//   rs  : 64
//   W2s : 128
//   b1s : 128
//   red : 2
constexpr int SMEM_FLOATS = Hh * W1S + (NTILE + 2) * Dd + NTILE * GSS + NTILE + Hh + Hh + 2;
constexpr int SMEM_BYTES  = SMEM_FLOATS * 4;   // 78344 B

extern __shared__ float smem[];

__global__ void zero_sum_kernel(float* out) {
    out[SUM_OFF + threadIdx.x] = 0.0f;
}

__global__ __launch_bounds__(256, 2)
void fused_kernel(const float* __restrict__ x,  const float* __restrict__ W1,
                  const float* __restrict__ b1, const float* __restrict__ W2,
                  const float* __restrict__ b2, float* __restrict__ out)
{
    float* W1s = smem;
    float* xs  = W1s + Hh * W1S;
    float* gs  = xs  + (NTILE + 2) * Dd;
    float* rs  = gs  + NTILE * GSS;
    float* W2s = rs  + NTILE;
    float* b1s = W2s + Hh;
    float* red = b1s + Hh;

    const int tid  = threadIdx.x;
    const int d    = blockIdx.y;
    const int tile = blockIdx.x;
    const int n0   = tile * NTILE;
    const int bb   = n0 / TTt;
    const int t0   = n0 % TTt;     // NTILE divides TTt -> tile never straddles a batch

    // ---------------- preamble: stage W1[d], x window, W2[d], b1[d] ----------------
    {
        const float* W1g = W1 + (size_t)d * Hh * INk;
        for (int idx = tid; idx < Hh * INk; idx += 256) {
            int h = idx / INk;
            int k = idx - h * INk;
            W1s[h * W1S + k] = W1g[idx];
        }
        const float* xg = x + ((size_t)bb * Tt + t0) * Dd;   // rows t0..t0+65 contiguous
        for (int idx = tid; idx < (NTILE + 2) * Dd; idx += 256)
            xs[idx] = xg[idx];
        if (tid < Hh) {
            W2s[tid] = W2[(size_t)d * Hh + tid];
            b1s[tid] = b1[(size_t)d * Hh + tid];
        }
        if (tid < NTILE) rs[tid] = 0.0f;
        if (tid < 2)     red[tid] = 0.0f;
    }
    __syncthreads();

    // ---------------- Phase A: pre = XX @ W1^T ; g, partial residual ----------------
    // thread tile: 4 n (ty in [0,16), i in [0,4)) x 8 h (tx in [0,16), h = tx + 16j)
    {
        const int tx = tid & 15;
        const int ty = tid >> 4;

        float acc[4][8];
        #pragma unroll
        for (int i = 0; i < 4; i++)
            #pragma unroll
            for (int j = 0; j < 8; j++)
                acc[i][j] = 0.0f;

        #pragma unroll 4
        for (int c = 0; c < 16; c++) {
            const int kb = c * 4;
            const int l  = kb >> 5;      // lag index for this k-chunk (0 or 1)
            const int d2 = kb & 31;
            float4 a4[4], w4[8];
            #pragma unroll
            for (int i = 0; i < 4; i++)
                a4[i] = *(const float4*)&xs[(ty * 4 + i + l) * Dd + d2];
            #pragma unroll
            for (int j = 0; j < 8; j++)
                w4[j] = *(const float4*)&W1s[(tx + 16 * j) * W1S + kb];
            #pragma unroll
            for (int i = 0; i < 4; i++) {
                #pragma unroll
                for (int j = 0; j < 8; j++) {
                    acc[i][j] = fmaf(a4[i].x, w4[j].x, acc[i][j]);
                    acc[i][j] = fmaf(a4[i].y, w4[j].y, acc[i][j]);
                    acc[i][j] = fmaf(a4[i].z, w4[j].z, acc[i][j]);
                    acc[i][j] = fmaf(a4[i].w, w4[j].w, acc[i][j]);
                }
            }
        }

        // k = 64 (yy term), bias, activation-derivative, g store, residual partials
        #pragma unroll
        for (int i = 0; i < 4; i++) {
            const int nl = ty * 4 + i;
            const float yy = xs[(nl + 2) * Dd + d];
            float rpart = 0.0f;
            #pragma unroll
            for (int j = 0; j < 8; j++) {
                const int h = tx + 16 * j;
                float pre = fmaf(yy, W1s[h * W1S + 64], acc[i][j]) + b1s[h];
                float g = (pre >= 0.0f) ? W2s[h] : SLOPE * W2s[h];
                rpart = fmaf(pre, g, rpart);      // act*W2 == pre*g
                gs[nl * GSS + h] = g;
            }
            atomicAdd(&rs[nl], rpart);
        }
    }
    __syncthreads();

    // residual output
    if (tid < NTILE) {
        out[RES_OFF + ((size_t)bb * TTt + t0 + tid) * Dd + d] = rs[tid] + b2[d];
    }

    // ---------------- Phase B: jac[:, 0:64] = g @ W1 ; write hist_jac ----------------
    // thread tile: 4 n (ny in [0,16), i in [0,4)) x 4 k (kx in [0,16), k = 4kx..4kx+3)
    {
        const int kx = tid & 15;
        const int ny = tid >> 4;

        float acc2[4][4];
        #pragma unroll
        for (int i = 0; i < 4; i++)
            #pragma unroll
            for (int j = 0; j < 4; j++)
                acc2[i][j] = 0.0f;

        #pragma unroll 2
        for (int hc = 0; hc < 32; hc++) {
            const int hb = hc * 4;
            float4 w4b[4];
            #pragma unroll
            for (int hh = 0; hh < 4; hh++)
                w4b[hh] = *(const float4*)&W1s[(hb + hh) * W1S + 4 * kx];
            #pragma unroll
            for (int i = 0; i < 4; i++) {
                const float4 gv = *(const float4*)&gs[(ny * 4 + i) * GSS + hb];
                acc2[i][0] = fmaf(gv.x, w4b[0].x, acc2[i][0]);
                acc2[i][1] = fmaf(gv.x, w4b[0].y, acc2[i][1]);
                acc2[i][2] = fmaf(gv.x, w4b[0].z, acc2[i][2]);
                acc2[i][3] = fmaf(gv.x, w4b[0].w, acc2[i][3]);
                acc2[i][0] = fmaf(gv.y, w4b[1].x, acc2[i][0]);
                acc2[i][1] = fmaf(gv.y, w4b[1].y, acc2[i][1]);
                acc2[i][2] = fmaf(gv.y, w4b[1].z, acc2[i][2]);
                acc2[i][3] = fmaf(gv.y, w4b[1].w, acc2[i][3]);
                acc2[i][0] = fmaf(gv.z, w4b[2].x, acc2[i][0]);
                acc2[i][1] = fmaf(gv.z, w4b[2].y, acc2[i][1]);
                acc2[i][2] = fmaf(gv.z, w4b[2].z, acc2[i][2]);
                acc2[i][3] = fmaf(gv.z, w4b[2].w, acc2[i][3]);
                acc2[i][0] = fmaf(gv.w, w4b[3].x, acc2[i][0]);
                acc2[i][1] = fmaf(gv.w, w4b[3].y, acc2[i][1]);
                acc2[i][2] = fmaf(gv.w, w4b[3].z, acc2[i][2]);
                acc2[i][3] = fmaf(gv.w, w4b[3].w, acc2[i][3]);
            }
        }

        #pragma unroll
        for (int i = 0; i < 4; i++) {
            const int n = n0 + ny * 4 + i;
            float4 v = make_float4(acc2[i][0], acc2[i][1], acc2[i][2], acc2[i][3]);
            *(float4*)&out[HIST_OFF + ((size_t)d * NTOT + n) * 64 + 4 * kx] = v;
        }
    }

    // ---------------- Phase B2: jac[:, 64] -> log|.| -> per-batch sum ----------------
    float lsum = 0.0f;
    if (tid < NTILE) {
        float jl = 0.0f;
        #pragma unroll 8
        for (int h = 0; h < Hh; h++)
            jl = fmaf(gs[tid * GSS + h], W1s[h * W1S + 64], jl);
        lsum = logf(fabsf(jl));
    }
    // warp reduce (threads >= 64 contribute 0)
    #pragma unroll
    for (int off = 16; off; off >>= 1)
        lsum += __shfl_down_sync(0xffffffffu, lsum, off);
    if (tid < NTILE && (tid & 31) == 0)
        atomicAdd(&red[0], lsum);
    __syncthreads();
    if (tid == 0)
        atomicAdd(&out[SUM_OFF + bb], red[0]);
}

extern "C" void kernel_launch(void* const* d_in, const int* in_sizes, int n_in,
                              void* d_out, int out_size) {
    const float* x  = (const float*)d_in[0];
    const float* W1 = (const float*)d_in[1];
    const float* b1 = (const float*)d_in[2];
    const float* W2 = (const float*)d_in[3];
    const float* b2 = (const float*)d_in[4];
    float* out = (float*)d_out;

    cudaFuncSetAttribute(fused_kernel, cudaFuncAttributeMaxDynamicSharedMemorySize, SMEM_BYTES);

    zero_sum_kernel<<<1, Bb>>>(out);
    fused_kernel<<<dim3(NTILES, Dd), 256, SMEM_BYTES>>>(x, W1, b1, W2, b2, out);
}

// round 4
// speedup vs baseline: 1.1893x; 1.1893x over previous
#include <cuda_runtime.h>
#include <math.h>
#include <stdint.h>

#define SLOPE 0.01f

// -------- problem constants --------
constexpr int Dd    = 32;
constexpr int Hh    = 128;
constexpr int Bb    = 64;
constexpr int Tt    = 514;
constexpr int TTt   = 512;
constexpr int NTOT  = Bb * TTt;          // 32768
constexpr int NTILE = 128;
constexpr int NTILES = NTOT / NTILE;     // 256

// output layout (reference return order, concatenated)
constexpr size_t RES_OFF  = 0;                        // (64,512,32)
constexpr size_t SUM_OFF  = (size_t)Bb * TTt * Dd;    // (64,)
constexpr size_t HIST_OFF = SUM_OFF + Bb;             // (32,32768,1,64)

// -------- shared offsets (u32 units) --------
constexpr int XWS   = 36;                 // x-window row stride
constexpr int W1SS  = 68;                 // W1 row stride (65 cols used)
constexpr int GS    = 132;                // g row stride (128 cols used)
constexpr int O_XWH   = 0;                               // 130*36 = 4680
constexpr int O_XWL   = O_XWH + 130 * XWS;               // 4680
constexpr int O_W1H   = O_XWL + 130 * XWS;               // 9360
constexpr int O_W1L   = O_W1H + Hh * W1SS;               // 18064
constexpr int O_G     = O_W1L + Hh * W1SS;               // 26768  (fp32 g, 128x132)
constexpr int O_WLAST = O_G   + NTILE * GS;              // 43664
constexpr int O_B1    = O_WLAST + 128;                   // 43792
constexpr int O_W2    = O_B1 + 128;                      // 43920
constexpr int O_YY    = O_W2 + 128;                      // 44048 (132)
constexpr int O_RS    = O_YY + 132;                      // 44180
constexpr int O_JS    = O_RS + 128;                      // 44308
constexpr int O_RED   = O_JS + 128;                      // 44436
constexpr int SMEM_U32 = O_RED + 4;                      // 44440
constexpr int SMEM_BYTES = SMEM_U32 * 4;                 // 177760

__device__ __forceinline__ uint32_t f2tf32(float f) {
    uint32_t u;
    asm("cvt.rna.tf32.f32 %0, %1;" : "=r"(u) : "f"(f));
    return u;
}

__device__ __forceinline__ void mma8(float* d, const uint32_t* a, uint32_t b0, uint32_t b1) {
    asm volatile(
        "mma.sync.aligned.m16n8k8.row.col.f32.tf32.tf32.f32 "
        "{%0,%1,%2,%3}, {%4,%5,%6,%7}, {%8,%9}, {%0,%1,%2,%3};"
        : "+f"(d[0]), "+f"(d[1]), "+f"(d[2]), "+f"(d[3])
        : "r"(a[0]), "r"(a[1]), "r"(a[2]), "r"(a[3]), "r"(b0), "r"(b1));
}

__global__ void zero_sum_kernel(float* out) { out[SUM_OFF + threadIdx.x] = 0.0f; }

extern __shared__ uint32_t smemu[];

__global__ __launch_bounds__(256, 1)
void fused_mma(const float* __restrict__ x,  const float* __restrict__ W1,
               const float* __restrict__ b1, const float* __restrict__ W2,
               const float* __restrict__ b2, float* __restrict__ out)
{
    float* sf = (float*)smemu;
    const int tid  = threadIdx.x;
    const int lane = tid & 31;
    const int w    = tid >> 5;
    const int lr   = lane >> 2;   // 0..7  (groupID)
    const int lc   = lane & 3;    // 0..3  (threadID_in_group)

    const int d  = blockIdx.x;
    const int n0 = blockIdx.y * NTILE;
    const int bb = n0 / TTt;
    const int t0 = n0 % TTt;

    // ---------------- preamble ----------------
    {
        const float* W1g = W1 + (size_t)d * Hh * 65;
        for (int idx = tid; idx < Hh * 65; idx += 256) {
            int h = idx / 65;
            int k = idx - h * 65;
            float v = W1g[idx];
            if (k == 64) {
                sf[O_WLAST + h] = v;
            } else {
                uint32_t hi = f2tf32(v);
                smemu[O_W1H + h * W1SS + k] = hi;
                smemu[O_W1L + h * W1SS + k] = f2tf32(v - __uint_as_float(hi));
            }
        }
        const float* xg = x + ((size_t)bb * Tt + t0) * Dd;
        for (int idx = tid; idx < 130 * 32; idx += 256) {
            int r = idx >> 5, c = idx & 31;
            float v = xg[idx];
            uint32_t hi = f2tf32(v);
            smemu[O_XWH + r * XWS + c] = hi;
            smemu[O_XWL + r * XWS + c] = f2tf32(v - __uint_as_float(hi));
            if (c == d) sf[O_YY + r] = v;
        }
        if (tid < 128) {
            sf[O_B1 + tid] = b1[(size_t)d * Hh + tid];
            sf[O_W2 + tid] = W2[(size_t)d * Hh + tid];
            sf[O_RS + tid] = 0.0f;
            sf[O_JS + tid] = 0.0f;
        }
        if (tid == 0) sf[O_RED] = 0.0f;
    }
    __syncthreads();

    // ---------------- GEMM A: pre[128n x 128h] = XX @ W1[:, :64]^T (3xTF32) ----------------
    // warp grid: 4 (n) x 2 (h); warp tile 32n x 64h
    const int nblk = (w & 3) * 32;
    const int hblk = (w >> 2) * 64;

    float acc[2][8][4];
    #pragma unroll
    for (int i = 0; i < 2; i++)
        #pragma unroll
        for (int j = 0; j < 8; j++)
            #pragma unroll
            for (int q = 0; q < 4; q++) acc[i][j][q] = 0.0f;

    #pragma unroll 2
    for (int s = 0; s < 8; s++) {
        const int l  = s >> 2;                  // lag for this k-chunk
        const int c0 = ((8 * s) & 31) + lc;     // column within x row
        uint32_t ah[2][4], al[2][4];
        #pragma unroll
        for (int i = 0; i < 2; i++) {
            int base = (nblk + 16 * i + lr + l) * XWS + c0;
            ah[i][0] = smemu[O_XWH + base];
            ah[i][1] = smemu[O_XWH + base + 8 * XWS];
            ah[i][2] = smemu[O_XWH + base + 4];
            ah[i][3] = smemu[O_XWH + base + 8 * XWS + 4];
            al[i][0] = smemu[O_XWL + base];
            al[i][1] = smemu[O_XWL + base + 8 * XWS];
            al[i][2] = smemu[O_XWL + base + 4];
            al[i][3] = smemu[O_XWL + base + 8 * XWS + 4];
        }
        #pragma unroll
        for (int j = 0; j < 8; j++) {
            int hb = (hblk + 8 * j + lr) * W1SS + 8 * s + lc;
            uint32_t bh0 = smemu[O_W1H + hb], bh1 = smemu[O_W1H + hb + 4];
            uint32_t bl0 = smemu[O_W1L + hb], bl1 = smemu[O_W1L + hb + 4];
            #pragma unroll
            for (int i = 0; i < 2; i++) {
                mma8(acc[i][j], ah[i], bh0, bh1);
                mma8(acc[i][j], ah[i], bl0, bl1);
                mma8(acc[i][j], al[i], bh0, bh1);
            }
        }
    }

    // ---------------- epilogue A: g (fp32 -> smem), residual + jac[:,64] partials -----------
    {
        float yyv[2][2], rp[2][2], jp[2][2];
        #pragma unroll
        for (int i = 0; i < 2; i++)
            #pragma unroll
            for (int ci = 0; ci < 2; ci++) {
                yyv[i][ci] = sf[O_YY + nblk + 16 * i + 8 * ci + lr + 2];
                rp[i][ci] = 0.0f;
                jp[i][ci] = 0.0f;
            }

        #pragma unroll
        for (int j = 0; j < 8; j++) {
            #pragma unroll
            for (int cj = 0; cj < 2; cj++) {
                const int h = hblk + 8 * j + 2 * lc + cj;
                const float wl = sf[O_WLAST + h];
                const float bv = sf[O_B1 + h];
                const float w2 = sf[O_W2 + h];
                #pragma unroll
                for (int i = 0; i < 2; i++) {
                    #pragma unroll
                    for (int ci = 0; ci < 2; ci++) {
                        float pre = fmaf(yyv[i][ci], wl, acc[i][j][2 * ci + cj]) + bv;
                        float g = (pre >= 0.0f) ? w2 : SLOPE * w2;
                        rp[i][ci] = fmaf(pre, g, rp[i][ci]);
                        jp[i][ci] = fmaf(g, wl, jp[i][ci]);
                        sf[O_G + (nblk + 16 * i + 8 * ci + lr) * GS + h] = g;
                    }
                }
            }
        }
        #pragma unroll
        for (int i = 0; i < 2; i++)
            #pragma unroll
            for (int ci = 0; ci < 2; ci++) {
                float r = rp[i][ci], jv = jp[i][ci];
                r += __shfl_xor_sync(0xffffffffu, r, 1);
                r += __shfl_xor_sync(0xffffffffu, r, 2);
                jv += __shfl_xor_sync(0xffffffffu, jv, 1);
                jv += __shfl_xor_sync(0xffffffffu, jv, 2);
                if (lc == 0) {
                    int row = nblk + 16 * i + 8 * ci + lr;
                    atomicAdd(&sf[O_RS + row], r);
                    atomicAdd(&sf[O_JS + row], jv);
                }
            }
    }
    __syncthreads();

    // residual + logdet outputs
    if (tid < 128) {
        const int n = tid;
        out[RES_OFF + ((size_t)(bb * TTt + t0 + n)) * Dd + d] = sf[O_RS + n] + __ldg(&b2[d]);
        float ls = logf(fabsf(sf[O_JS + n]));
        #pragma unroll
        for (int o = 16; o; o >>= 1) ls += __shfl_down_sync(0xffffffffu, ls, o);
        if (lane == 0) atomicAdd(&sf[O_RED], ls);
    }

    // ---------------- GEMM B: jac[128n x 64k] = g @ W1[:, :64] (3xTF32) ----------------
    // warp grid: 4 (n) x 2 (kcol); warp tile 32n x 32k
    const int nblk2 = (w & 3) * 32;
    const int kblk  = (w >> 2) * 32;

    float acc2[2][4][4];
    #pragma unroll
    for (int i = 0; i < 2; i++)
        #pragma unroll
        for (int j = 0; j < 4; j++)
            #pragma unroll
            for (int q = 0; q < 4; q++) acc2[i][j][q] = 0.0f;

    #pragma unroll 2
    for (int s = 0; s < 16; s++) {
        const int h0 = 8 * s;
        uint32_t gh[2][4], gl[2][4];
        #pragma unroll
        for (int i = 0; i < 2; i++) {
            int base = (nblk2 + 16 * i + lr) * GS + h0 + lc;
            float g0 = sf[O_G + base];
            float g1 = sf[O_G + base + 8 * GS];
            float g2 = sf[O_G + base + 4];
            float g3 = sf[O_G + base + 8 * GS + 4];
            gh[i][0] = f2tf32(g0); gl[i][0] = f2tf32(g0 - __uint_as_float(gh[i][0]));
            gh[i][1] = f2tf32(g1); gl[i][1] = f2tf32(g1 - __uint_as_float(gh[i][1]));
            gh[i][2] = f2tf32(g2); gl[i][2] = f2tf32(g2 - __uint_as_float(gh[i][2]));
            gh[i][3] = f2tf32(g3); gl[i][3] = f2tf32(g3 - __uint_as_float(gh[i][3]));
        }
        #pragma unroll
        for (int j = 0; j < 4; j++) {
            int bbase = (h0 + lc) * W1SS + kblk + 8 * j + lr;
            uint32_t bh0 = smemu[O_W1H + bbase], bh1 = smemu[O_W1H + bbase + 4 * W1SS];
            uint32_t bl0 = smemu[O_W1L + bbase], bl1 = smemu[O_W1L + bbase + 4 * W1SS];
            #pragma unroll
            for (int i = 0; i < 2; i++) {
                mma8(acc2[i][j], gh[i], bh0, bh1);
                mma8(acc2[i][j], gh[i], bl0, bl1);
                mma8(acc2[i][j], gl[i], bh0, bh1);
            }
        }
    }

    // write hist_jac
    #pragma unroll
    for (int i = 0; i < 2; i++) {
        #pragma unroll
        for (int ci = 0; ci < 2; ci++) {
            const int r = nblk2 + 16 * i + 8 * ci + lr;
            float* hb = out + HIST_OFF + ((size_t)d * NTOT + n0 + r) * 64;
            #pragma unroll
            for (int j = 0; j < 4; j++) {
                const int col = kblk + 8 * j + 2 * lc;
                float2 v = make_float2(acc2[i][j][2 * ci], acc2[i][j][2 * ci + 1]);
                *(float2*)(hb + col) = v;
            }
        }
    }

    __syncthreads();
    if (tid == 0) atomicAdd(&out[SUM_OFF + bb], sf[O_RED]);
}

extern "C" void kernel_launch(void* const* d_in, const int* in_sizes, int n_in,
                              void* d_out, int out_size) {
    const float* x  = (const float*)d_in[0];
    const float* W1 = (const float*)d_in[1];
    const float* b1 = (const float*)d_in[2];
    const float* W2 = (const float*)d_in[3];
    const float* b2 = (const float*)d_in[4];
    float* out = (float*)d_out;

    cudaFuncSetAttribute(fused_mma, cudaFuncAttributeMaxDynamicSharedMemorySize, SMEM_BYTES);

    zero_sum_kernel<<<1, Bb>>>(out);
    fused_mma<<<dim3(Dd, NTILES), 256, SMEM_BYTES>>>(x, W1, b1, W2, b2, out);
}

// round 5
// speedup vs baseline: 1.9452x; 1.6356x over previous
#include <cuda_runtime.h>
#include <math.h>
#include <stdint.h>

#define SLOPE 0.01f
constexpr float RCOEF = 1.0f - SLOPE;

// -------- problem constants --------
constexpr int Dd    = 32;
constexpr int Hh    = 128;
constexpr int Bb    = 64;
constexpr int Tt    = 514;
constexpr int TTt   = 512;
constexpr int NTOT  = Bb * TTt;          // 32768
constexpr int NTILE = 128;
constexpr int NTILES = NTOT / NTILE;     // 256

// output layout (reference return order, concatenated)
constexpr size_t RES_OFF  = 0;                        // (64,512,32)
constexpr size_t SUM_OFF  = (size_t)Bb * TTt * Dd;    // (64,)
constexpr size_t HIST_OFF = SUM_OFF + Bb;             // (32,32768,1,64)

// -------- shared offsets (u32 units) --------
constexpr int XWS = 36;                  // x-window row stride (bank: 4*lr+lc, conflict-free)
constexpr int W1S = 68;                  // W1 row stride
constexpr int O_XW    = 0;                               // 130*36 fp32
constexpr int O_W1    = O_XW + 130 * XWS;                // 4680: 128*68 fp32 (cols 0..63)
constexpr int O_MASK  = O_W1 + Hh * W1S;                 // 13384: 128 rows x 4 words
constexpr int O_S     = O_MASK + 512;                    // 13896: 64 colsums
constexpr int O_WLAST = O_S + 64;                        // 13960
constexpr int O_B1    = O_WLAST + 128;                   // 14088
constexpr int O_W2    = O_B1 + 128;                      // 14216
constexpr int O_YY    = O_W2 + 128;                      // 14344 (132)
constexpr int O_RS    = O_YY + 132;                      // 14476
constexpr int O_JS    = O_RS + 128;                      // 14604
constexpr int O_RED   = O_JS + 128;                      // 14732
constexpr int SMEM_U32 = O_RED + 4;                      // 14736
constexpr int SMEM_BYTES = SMEM_U32 * 4;                 // 58944

__device__ __forceinline__ uint32_t f2tf32(float f) {
    uint32_t u;
    asm("cvt.rna.tf32.f32 %0, %1;" : "=r"(u) : "f"(f));
    return u;
}
// split fp32 -> (hi, lo) tf32 pair
__device__ __forceinline__ void split_tf32(float v, uint32_t& hi, uint32_t& lo) {
    hi = f2tf32(v);
    lo = f2tf32(v - __uint_as_float(hi));
}
__device__ __forceinline__ uint32_t bit2one(uint32_t w, int b) {
    return ((w >> b) & 1u) ? 0x3F800000u : 0u;   // 1.0f or 0.0f (exact in tf32)
}

__device__ __forceinline__ void mma8(float* d, const uint32_t* a, uint32_t b0, uint32_t b1) {
    asm volatile(
        "mma.sync.aligned.m16n8k8.row.col.f32.tf32.tf32.f32 "
        "{%0,%1,%2,%3}, {%4,%5,%6,%7}, {%8,%9}, {%0,%1,%2,%3};"
        : "+f"(d[0]), "+f"(d[1]), "+f"(d[2]), "+f"(d[3])
        : "r"(a[0]), "r"(a[1]), "r"(a[2]), "r"(a[3]), "r"(b0), "r"(b1));
}

__global__ void zero_sum_kernel(float* out) { out[SUM_OFF + threadIdx.x] = 0.0f; }

extern __shared__ uint32_t smemu[];

__global__ __launch_bounds__(256, 2)
void fused_mma(const float* __restrict__ x,  const float* __restrict__ W1,
               const float* __restrict__ b1, const float* __restrict__ W2,
               const float* __restrict__ b2, float* __restrict__ out)
{
    float* sf = (float*)smemu;
    const int tid  = threadIdx.x;
    const int lane = tid & 31;
    const int w    = tid >> 5;
    const int lr   = lane >> 2;   // 0..7
    const int lc   = lane & 3;    // 0..3

    const int d  = blockIdx.x;
    const int n0 = blockIdx.y * NTILE;
    const int bb = n0 / TTt;
    const int t0 = n0 % TTt;

    // ---------------- preamble: stage fp32 tiles ----------------
    {
        const float* W1g = W1 + (size_t)d * Hh * 65;
        for (int idx = tid; idx < Hh * 65; idx += 256) {
            int h = idx / 65;
            int k = idx - h * 65;
            float v = W1g[idx];
            if (k == 64) sf[O_WLAST + h] = v;
            else         sf[O_W1 + h * W1S + k] = v;
        }
        const float* xg = x + ((size_t)bb * Tt + t0) * Dd;
        for (int idx = tid; idx < 130 * 32; idx += 256) {
            int r = idx >> 5, c = idx & 31;
            float v = xg[idx];
            sf[O_XW + r * XWS + c] = v;
            if (c == d) sf[O_YY + r] = v;
        }
        if (tid < 128) {
            sf[O_B1 + tid] = b1[(size_t)d * Hh + tid];
            sf[O_W2 + tid] = W2[(size_t)d * Hh + tid];
            sf[O_RS + tid] = 0.0f;
            sf[O_JS + tid] = 0.0f;
        }
        if (tid == 0) sf[O_RED] = 0.0f;
    }
    __syncthreads();

    // colsums S[k] = sum_h w2[h]*W1[h][k]   (threads 0..63; read only before GEMM-B barrier)
    if (tid < 64) {
        float s = 0.0f;
        #pragma unroll 8
        for (int h = 0; h < Hh; h++)
            s = fmaf(sf[O_W2 + h], sf[O_W1 + h * W1S + tid], s);
        sf[O_S + tid] = s;
    }

    // ---------------- GEMM A: pre[128n x 128h] = XX @ W1[:, :64]^T (3xTF32) ----------------
    const int nblk = (w & 3) * 32;
    const int hblk = (w >> 2) * 64;

    float acc[2][8][4];
    #pragma unroll
    for (int i = 0; i < 2; i++)
        #pragma unroll
        for (int j = 0; j < 8; j++)
            #pragma unroll
            for (int q = 0; q < 4; q++) acc[i][j][q] = 0.0f;

    #pragma unroll 2
    for (int s = 0; s < 8; s++) {
        const int l  = s >> 2;
        const int c0 = ((8 * s) & 31) + lc;
        uint32_t ah[2][4], al[2][4];
        #pragma unroll
        for (int i = 0; i < 2; i++) {
            int base = O_XW + (nblk + 16 * i + lr + l) * XWS + c0;
            split_tf32(sf[base],               ah[i][0], al[i][0]);
            split_tf32(sf[base + 8 * XWS],     ah[i][1], al[i][1]);
            split_tf32(sf[base + 4],           ah[i][2], al[i][2]);
            split_tf32(sf[base + 8 * XWS + 4], ah[i][3], al[i][3]);
        }
        #pragma unroll
        for (int j = 0; j < 8; j++) {
            int hb = O_W1 + (hblk + 8 * j + lr) * W1S + 8 * s + lc;
            uint32_t bh0, bl0, bh1, bl1;
            split_tf32(sf[hb],     bh0, bl0);
            split_tf32(sf[hb + 4], bh1, bl1);
            #pragma unroll
            for (int i = 0; i < 2; i++) {
                mma8(acc[i][j], ah[i], bh0, bh1);
                mma8(acc[i][j], ah[i], bl0, bl1);
                mma8(acc[i][j], al[i], bh0, bh1);
            }
        }
    }

    // ---------------- epilogue A: mask bits, residual + jac[:,64] partials ----------------
    {
        #pragma unroll
        for (int i = 0; i < 2; i++) {
            #pragma unroll
            for (int ci = 0; ci < 2; ci++) {
                const int row = nblk + 16 * i + 8 * ci + lr;
                const float yyv = sf[O_YY + row + 2];
                float rp = 0.0f, jp = 0.0f;
                uint32_t m0 = 0, m1 = 0;
                #pragma unroll
                for (int j = 0; j < 8; j++) {
                    #pragma unroll
                    for (int cj = 0; cj < 2; cj++) {
                        const int h = hblk + 8 * j + 2 * lc + cj;
                        const float wl = sf[O_WLAST + h];
                        float pre = fmaf(yyv, wl, acc[i][j][2 * ci + cj]) + sf[O_B1 + h];
                        float g = (pre >= 0.0f) ? sf[O_W2 + h] : SLOPE * sf[O_W2 + h];
                        rp = fmaf(pre, g, rp);
                        jp = fmaf(g, wl, jp);
                        uint32_t bit = (pre >= 0.0f) ? (1u << (8 * (j & 3) + 2 * lc + cj)) : 0u;
                        if (j < 4) m0 |= bit; else m1 |= bit;
                    }
                }
                // combine mask across lc lanes, store by lc==0
                m0 |= __shfl_xor_sync(0xffffffffu, m0, 1);
                m0 |= __shfl_xor_sync(0xffffffffu, m0, 2);
                m1 |= __shfl_xor_sync(0xffffffffu, m1, 1);
                m1 |= __shfl_xor_sync(0xffffffffu, m1, 2);
                if (lc == 0) {
                    smemu[O_MASK + row * 4 + (hblk >> 5)]     = m0;
                    smemu[O_MASK + row * 4 + (hblk >> 5) + 1] = m1;
                }
                // reduce residual / jl partials across lc
                rp += __shfl_xor_sync(0xffffffffu, rp, 1);
                rp += __shfl_xor_sync(0xffffffffu, rp, 2);
                jp += __shfl_xor_sync(0xffffffffu, jp, 1);
                jp += __shfl_xor_sync(0xffffffffu, jp, 2);
                if (lc == 0) {
                    atomicAdd(&sf[O_RS + row], rp);
                    atomicAdd(&sf[O_JS + row], jp);
                }
            }
        }
    }
    __syncthreads();

    // residual + logdet outputs
    if (tid < 128) {
        const int n = tid;
        out[RES_OFF + ((size_t)(bb * TTt + t0 + n)) * Dd + d] = sf[O_RS + n] + __ldg(&b2[d]);
        float ls = logf(fabsf(sf[O_JS + n]));
        #pragma unroll
        for (int o = 16; o; o >>= 1) ls += __shfl_down_sync(0xffffffffu, ls, o);
        if (lane == 0) atomicAdd(&sf[O_RED], ls);
    }

    // ---------------- GEMM B: jac = SLOPE*S + RCOEF*(mask @ (w2 .* W1)) ----------------
    const int nblk2 = (w & 3) * 32;
    const int kblk  = (w >> 2) * 32;

    uint32_t mA[2][4], mB[2][4];
    #pragma unroll
    for (int i = 0; i < 2; i++) {
        const int r1 = nblk2 + 16 * i + lr;
        #pragma unroll
        for (int q = 0; q < 4; q++) {
            mA[i][q] = smemu[O_MASK + r1 * 4 + q];
            mB[i][q] = smemu[O_MASK + (r1 + 8) * 4 + q];
        }
    }

    float acc2[2][4][4];
    #pragma unroll
    for (int i = 0; i < 2; i++)
        #pragma unroll
        for (int j = 0; j < 4; j++)
            #pragma unroll
            for (int q = 0; q < 4; q++) acc2[i][j][q] = 0.0f;

    #pragma unroll 4
    for (int s = 0; s < 16; s++) {
        const int bit0 = 8 * (s & 3) + lc;
        const int ws   = s >> 2;
        uint32_t a[2][4];
        #pragma unroll
        for (int i = 0; i < 2; i++) {
            a[i][0] = bit2one(mA[i][ws], bit0);
            a[i][1] = bit2one(mB[i][ws], bit0);
            a[i][2] = bit2one(mA[i][ws], bit0 + 4);
            a[i][3] = bit2one(mB[i][ws], bit0 + 4);
        }
        const float w2a = sf[O_W2 + 8 * s + lc];
        const float w2b = sf[O_W2 + 8 * s + lc + 4];
        #pragma unroll
        for (int j = 0; j < 4; j++) {
            const int kp = kblk + 8 * j + lr;
            float u0 = sf[O_W1 + (8 * s + lc) * W1S + kp] * w2a;
            float u1 = sf[O_W1 + (8 * s + lc + 4) * W1S + kp] * w2b;
            uint32_t bh0, bl0, bh1, bl1;
            split_tf32(u0, bh0, bl0);
            split_tf32(u1, bh1, bl1);
            #pragma unroll
            for (int i = 0; i < 2; i++) {
                mma8(acc2[i][j], a[i], bh0, bh1);
                mma8(acc2[i][j], a[i], bl0, bl1);
            }
        }
    }

    // write hist_jac: jac = SLOPE*S[k] + RCOEF*acc2
    #pragma unroll
    for (int i = 0; i < 2; i++) {
        #pragma unroll
        for (int ci = 0; ci < 2; ci++) {
            const int r = nblk2 + 16 * i + 8 * ci + lr;
            float* hb = out + HIST_OFF + ((size_t)d * NTOT + n0 + r) * 64;
            #pragma unroll
            for (int j = 0; j < 4; j++) {
                const int col = kblk + 8 * j + 2 * lc;
                const float s0 = sf[O_S + col];
                const float s1 = sf[O_S + col + 1];
                float2 v = make_float2(fmaf(RCOEF, acc2[i][j][2 * ci],     SLOPE * s0),
                                       fmaf(RCOEF, acc2[i][j][2 * ci + 1], SLOPE * s1));
                *(float2*)(hb + col) = v;
            }
        }
    }

    __syncthreads();
    if (tid == 0) atomicAdd(&out[SUM_OFF + bb], sf[O_RED]);
}

extern "C" void kernel_launch(void* const* d_in, const int* in_sizes, int n_in,
                              void* d_out, int out_size) {
    const float* x  = (const float*)d_in[0];
    const float* W1 = (const float*)d_in[1];
    const float* b1 = (const float*)d_in[2];
    const float* W2 = (const float*)d_in[3];
    const float* b2 = (const float*)d_in[4];
    float* out = (float*)d_out;

    cudaFuncSetAttribute(fused_mma, cudaFuncAttributeMaxDynamicSharedMemorySize, SMEM_BYTES);

    zero_sum_kernel<<<1, Bb>>>(out);
    fused_mma<<<dim3(Dd, NTILES), 256, SMEM_BYTES>>>(x, W1, b1, W2, b2, out);
}